// round 4
// baseline (speedup 1.0000x reference)
#include <cuda_runtime.h>
#include <cuda_bf16.h>
#include <cstdint>
#include <cstddef>

#define VOCAB   100000
#define EMB     256
#define NS      256
#define BATCH   16384
#define MBLK    64               // batch rows per block
#define NSB     64               // sampled columns per block
#define NSPLIT  (NS / NSB)       // 4
#define NBLK    ((BATCH / MBLK) * NSPLIT)   // 1024
#define KPAD    264              // bf16 elems per smem row (256+8 -> conflict-free ldmatrix)

__device__ float g_partials[NBLK];
__device__ int   g_count = 0;

__device__ __forceinline__ float softplus_fast(float x) {
    return fmaxf(x, 0.0f) + __logf(1.0f + __expf(-fabsf(x)));
}

__device__ __forceinline__ uint32_t smem_u32(const void* p) {
    return (uint32_t)__cvta_generic_to_shared(p);
}

__device__ __forceinline__ void ldsm_x4(uint32_t& r0, uint32_t& r1, uint32_t& r2, uint32_t& r3,
                                        uint32_t addr) {
    asm volatile("ldmatrix.sync.aligned.m8n8.x4.shared.b16 {%0,%1,%2,%3}, [%4];"
                 : "=r"(r0), "=r"(r1), "=r"(r2), "=r"(r3) : "r"(addr));
}

__device__ __forceinline__ void mma_bf16(float& c0, float& c1, float& c2, float& c3,
                                         uint32_t a0, uint32_t a1, uint32_t a2, uint32_t a3,
                                         uint32_t b0, uint32_t b1) {
    asm volatile("mma.sync.aligned.m16n8k16.row.col.f32.bf16.bf16.f32 "
                 "{%0,%1,%2,%3}, {%4,%5,%6,%7}, {%8,%9}, {%0,%1,%2,%3};"
                 : "+f"(c0), "+f"(c1), "+f"(c2), "+f"(c3)
                 : "r"(a0), "r"(a1), "r"(a2), "r"(a3), "r"(b0), "r"(b1));
}

__global__ void __launch_bounds__(256, 3) w2v_fused(
    const float* __restrict__ emb,
    const float* __restrict__ ncew,
    const float* __restrict__ nceb,
    const int* __restrict__ inputs,
    const int* __restrict__ labels,
    const int* __restrict__ sids,
    float* __restrict__ out)
{
    extern __shared__ unsigned char smem_raw[];
    __nv_bfloat16* sA = (__nv_bfloat16*)smem_raw;             // [MBLK][KPAD]
    __nv_bfloat16* sW = sA + MBLK * KPAD;                     // [NSB][KPAD]
    float* sCorr = (float*)(sW + (size_t)NSB * KPAD);         // [NSB]
    int*   sRow  = (int*)(sCorr + NSB);                       // [MBLK]
    float* sRed  = (float*)(sRow + MBLK);                     // [8]

    const int tid  = threadIdx.x;
    const int bid  = blockIdx.x;
    const int rb   = bid >> 2;            // row-block 0..255
    const int ns   = bid & 3;             // sample quarter 0..3
    const int row0 = rb * MBLK;
    const int s0   = ns * NSB;
    const float INV_LOGV = 1.0f / logf((float)VOCAB + 1.0f);

    if (tid < MBLK) sRow[tid] = inputs[row0 + tid];
    if (tid < NSB) {
        int s = sids[s0 + tid];
        float p = (logf((float)s + 2.0f) - logf((float)s + 1.0f)) * INV_LOGV;
        sCorr[tid] = nceb[s] - logf((float)NS * p);
    }
    __syncthreads();

    // ---- Gather embed rows: bf16 -> smem A; fp32 -> out for my 16 owned rows ----
    #pragma unroll
    for (int it = 0; it < MBLK * (EMB / 4) / 256; it++) {   // 16 iters
        int i = it * 256 + tid;
        int r = i >> 6, c4 = i & 63;
        float4 v = __ldg((const float4*)(emb + (size_t)sRow[r] * EMB + c4 * 4));
        if ((r >> 4) == ns)   // each sample-quarter block writes 16 of the 64 rows
            ((float4*)out)[(size_t)(row0 + r) * (EMB / 4) + c4] = v;
        __nv_bfloat162* d = (__nv_bfloat162*)(sA + r * KPAD + c4 * 4);
        d[0] = __floats2bfloat162_rn(v.x, v.y);
        d[1] = __floats2bfloat162_rn(v.z, v.w);
    }
    // ---- Gather my 64 sampled weight rows -> smem W (bf16) ----
    #pragma unroll
    for (int it = 0; it < NSB * (EMB / 4) / 256; it++) {    // 16 iters
        int i = it * 256 + tid;
        int r = i >> 6, c4 = i & 63;
        int s = sids[s0 + r];
        float4 v = __ldg((const float4*)(ncew + (size_t)s * EMB + c4 * 4));
        __nv_bfloat162* d = (__nv_bfloat162*)(sW + r * KPAD + c4 * 4);
        d[0] = __floats2bfloat162_rn(v.x, v.y);
        d[1] = __floats2bfloat162_rn(v.z, v.w);
    }

    const int warp = tid >> 5;
    const int lane = tid & 31;

    // ---- True logits: this block handles 16 of its 64 rows (2 per warp) ----
    float tacc = 0.0f;
    #pragma unroll
    for (int i = 0; i < 2; i++) {
        int lr = ns * 16 + warp * 2 + i;
        int gr = row0 + lr;
        int lab = labels[gr];
        const float* er = emb  + (size_t)sRow[lr] * EMB;   // L1/L2-hot from gather
        const float* wr = ncew + (size_t)lab * EMB;
        int e0 = lane * 8;
        float4 a0 = __ldg((const float4*)(er + e0));
        float4 a1 = __ldg((const float4*)(er + e0 + 4));
        float4 b0 = __ldg((const float4*)(wr + e0));
        float4 b1 = __ldg((const float4*)(wr + e0 + 4));
        float s = a0.x * b0.x;
        s = fmaf(a0.y, b0.y, s); s = fmaf(a0.z, b0.z, s); s = fmaf(a0.w, b0.w, s);
        s = fmaf(a1.x, b1.x, s); s = fmaf(a1.y, b1.y, s);
        s = fmaf(a1.z, b1.z, s); s = fmaf(a1.w, b1.w, s);
        #pragma unroll
        for (int o = 16; o; o >>= 1) s += __shfl_xor_sync(0xFFFFFFFFu, s, o);
        if (lane == 0) {
            float p = (logf((float)lab + 2.0f) - logf((float)lab + 1.0f)) * INV_LOGV;
            float t = s + nceb[lab] - logf((float)NS * p);
            tacc += softplus_fast(-t);    // sigmoid_xent(t, 1)
        }
    }
    __syncthreads();

    // ---- Sampled logits: warp (wm, wn) owns 16 rows x 32 samples ----
    const int wm = warp & 3;
    const int wn = warp >> 2;
    const int mrow  = wm * 16;
    const int nbase = wn * 32;

    float acc[4][4];
    #pragma unroll
    for (int n = 0; n < 4; n++) {
        acc[n][0] = 0.f; acc[n][1] = 0.f; acc[n][2] = 0.f; acc[n][3] = 0.f;
    }

    const int mi = lane >> 3;   // ldmatrix sub-tile index 0..3
    const int arow = mrow + (mi & 1) * 8 + (lane & 7);
    const int acolb = (mi >> 1) * 8;
    const int bRow = nbase + (mi >> 1) * 8 + (lane & 7);   // +nn*16 inside loop
    const int bcolb = (mi & 1) * 8;

    #pragma unroll
    for (int k = 0; k < EMB; k += 16) {
        uint32_t a0, a1, a2, a3;
        ldsm_x4(a0, a1, a2, a3, smem_u32(sA + arow * KPAD + k + acolb));
        #pragma unroll
        for (int nn = 0; nn < 2; nn++) {
            uint32_t b0, b1, b2, b3;   // {b0,b1}=n8-tile 2nn, {b2,b3}=n8-tile 2nn+1
            ldsm_x4(b0, b1, b2, b3, smem_u32(sW + (bRow + nn * 16) * KPAD + k + bcolb));
            mma_bf16(acc[2*nn  ][0], acc[2*nn  ][1], acc[2*nn  ][2], acc[2*nn  ][3],
                     a0, a1, a2, a3, b0, b1);
            mma_bf16(acc[2*nn+1][0], acc[2*nn+1][1], acc[2*nn+1][2], acc[2*nn+1][3],
                     a0, a1, a2, a3, b2, b3);
        }
    }

    // ---- Epilogue: fast softplus(logit + corr), thread-local sum ----
    const int q = lane & 3;
    float local = tacc;
    #pragma unroll
    for (int n = 0; n < 4; n++) {
        int c0 = nbase + n * 8 + q * 2;
        float k0 = sCorr[c0], k1 = sCorr[c0 + 1];
        local += softplus_fast(acc[n][0] + k0) + softplus_fast(acc[n][1] + k1)
               + softplus_fast(acc[n][2] + k0) + softplus_fast(acc[n][3] + k1);
    }

    // ---- Deterministic block reduction -> per-block partial ----
    #pragma unroll
    for (int o = 16; o; o >>= 1) local += __shfl_xor_sync(0xFFFFFFFFu, local, o);
    if (lane == 0) sRed[warp] = local;
    __syncthreads();
    __shared__ bool sLast;
    if (tid == 0) {
        float v = 0.f;
        #pragma unroll
        for (int w = 0; w < 8; w++) v += sRed[w];
        g_partials[bid] = v;
        __threadfence();
        int old = atomicAdd(&g_count, 1);
        sLast = (old == NBLK - 1);
    }
    __syncthreads();

    // ---- Last block folds all partials into the scalar (deterministic tree) ----
    if (sLast) {
        __threadfence();
        float v = g_partials[tid] + g_partials[tid + 256]
                + g_partials[tid + 512] + g_partials[tid + 768];
        #pragma unroll
        for (int o = 16; o; o >>= 1) v += __shfl_xor_sync(0xFFFFFFFFu, v, o);
        if (lane == 0) sRed[warp] = v;
        __syncthreads();
        if (tid == 0) {
            float t = 0.f;
            #pragma unroll
            for (int w = 0; w < 8; w++) t += sRed[w];
            out[(size_t)BATCH * EMB] = t * (1.0f / (float)BATCH);
            g_count = 0;   // reset for next graph replay
        }
    }
}

extern "C" void kernel_launch(void* const* d_in, const int* in_sizes, int n_in,
                              void* d_out, int out_size) {
    const float* emb    = (const float*)d_in[0];
    const float* ncew   = (const float*)d_in[1];
    const float* nceb   = (const float*)d_in[2];
    const int*   inputs = (const int*)d_in[3];
    const int*   labels = (const int*)d_in[4];
    const int*   sids   = (const int*)d_in[5];
    float* out = (float*)d_out;

    size_t smem = (size_t)(MBLK + NSB) * KPAD * sizeof(__nv_bfloat16)
                + (size_t)NSB * sizeof(float)
                + (size_t)MBLK * sizeof(int)
                + 8 * sizeof(float);
    cudaFuncSetAttribute(w2v_fused, cudaFuncAttributeMaxDynamicSharedMemorySize, (int)smem);
    w2v_fused<<<NBLK, 256, smem>>>(emb, ncew, nceb, inputs, labels, sids, out);
}

// round 5
// speedup vs baseline: 1.0589x; 1.0589x over previous
#include <cuda_runtime.h>
#include <cuda_bf16.h>
#include <cstdint>
#include <cstddef>

#define VOCAB   100000
#define EMB     256
#define NS      256
#define BATCH   16384
#define MBLK    64               // batch rows per block
#define NSB     128              // sampled columns per block
#define NSPLIT  (NS / NSB)       // 2
#define NBLK    ((BATCH / MBLK) * NSPLIT)   // 512
#define KPAD    264              // bf16 elems per smem row (256+8 -> conflict-free ldmatrix)

__device__ float g_partials[NBLK];
__device__ int   g_count = 0;

__device__ __forceinline__ float softplus_fast(float x) {
    return fmaxf(x, 0.0f) + __logf(1.0f + __expf(-fabsf(x)));
}

__device__ __forceinline__ uint32_t smem_u32(const void* p) {
    return (uint32_t)__cvta_generic_to_shared(p);
}

__device__ __forceinline__ void ldsm_x4(uint32_t& r0, uint32_t& r1, uint32_t& r2, uint32_t& r3,
                                        uint32_t addr) {
    asm volatile("ldmatrix.sync.aligned.m8n8.x4.shared.b16 {%0,%1,%2,%3}, [%4];"
                 : "=r"(r0), "=r"(r1), "=r"(r2), "=r"(r3) : "r"(addr));
}

__device__ __forceinline__ void mma_bf16(float& c0, float& c1, float& c2, float& c3,
                                         uint32_t a0, uint32_t a1, uint32_t a2, uint32_t a3,
                                         uint32_t b0, uint32_t b1) {
    asm volatile("mma.sync.aligned.m16n8k16.row.col.f32.bf16.bf16.f32 "
                 "{%0,%1,%2,%3}, {%4,%5,%6,%7}, {%8,%9}, {%0,%1,%2,%3};"
                 : "+f"(c0), "+f"(c1), "+f"(c2), "+f"(c3)
                 : "r"(a0), "r"(a1), "r"(a2), "r"(a3), "r"(b0), "r"(b1));
}

__global__ void __launch_bounds__(256, 2) w2v_fused(
    const float* __restrict__ emb,
    const float* __restrict__ ncew,
    const float* __restrict__ nceb,
    const int* __restrict__ inputs,
    const int* __restrict__ labels,
    const int* __restrict__ sids,
    float* __restrict__ out)
{
    extern __shared__ unsigned char smem_raw[];
    __nv_bfloat16* sA = (__nv_bfloat16*)smem_raw;             // [MBLK][KPAD]
    __nv_bfloat16* sW = sA + MBLK * KPAD;                     // [NSB][KPAD]
    float* sCorr = (float*)(sW + (size_t)NSB * KPAD);         // [NSB]
    int*   sRow  = (int*)(sCorr + NSB);                       // [MBLK]
    float* sRed  = (float*)(sRow + MBLK);                     // [8]

    const int tid  = threadIdx.x;
    const int bid  = blockIdx.x;
    const int rb   = bid >> 1;            // row-block 0..255
    const int ns   = bid & 1;             // sample half 0/1
    const int row0 = rb * MBLK;
    const int s0   = ns * NSB;
    const float INV_LOGV = 1.0f / logf((float)VOCAB + 1.0f);

    if (tid < MBLK) sRow[tid] = inputs[row0 + tid];
    if (tid < NSB) {
        int s = sids[s0 + tid];
        float p = (logf((float)s + 2.0f) - logf((float)s + 1.0f)) * INV_LOGV;
        sCorr[tid] = nceb[s] - logf((float)NS * p);
    }
    __syncthreads();

    const int warp = tid >> 5;
    const int lane = tid & 31;

    // ---- Prefetch true-logit label-weight rows (cold DRAM) FIRST; their
    //      latency hides under the gather burst below. 4 rows/warp. ----
    int   labv[4];
    float4 tb0[4], tb1[4];
    #pragma unroll
    for (int i = 0; i < 4; i++) {
        int lr = ns * 32 + warp * 4 + i;
        labv[i] = labels[row0 + lr];
        const float* wr = ncew + (size_t)labv[i] * EMB + lane * 8;
        tb0[i] = __ldg((const float4*)wr);
        tb1[i] = __ldg((const float4*)(wr + 4));
    }

    // ---- Gather embed rows: bf16 -> smem A; fp32 -> out for my half of rows ----
    #pragma unroll
    for (int it = 0; it < MBLK * (EMB / 4) / 256; it++) {   // 16 iters
        int i = it * 256 + tid;
        int r = i >> 6, c4 = i & 63;
        float4 v = __ldg((const float4*)(emb + (size_t)sRow[r] * EMB + c4 * 4));
        if ((r >> 5) == ns)
            ((float4*)out)[(size_t)(row0 + r) * (EMB / 4) + c4] = v;
        __nv_bfloat162* d = (__nv_bfloat162*)(sA + r * KPAD + c4 * 4);
        d[0] = __floats2bfloat162_rn(v.x, v.y);
        d[1] = __floats2bfloat162_rn(v.z, v.w);
    }
    // ---- Gather my 128 sampled weight rows -> smem W (bf16) ----
    #pragma unroll
    for (int it = 0; it < NSB * (EMB / 4) / 256; it++) {    // 32 iters
        int i = it * 256 + tid;
        int r = i >> 6, c4 = i & 63;
        int s = sids[s0 + r];
        float4 v = __ldg((const float4*)(ncew + (size_t)s * EMB + c4 * 4));
        __nv_bfloat162* d = (__nv_bfloat162*)(sW + r * KPAD + c4 * 4);
        d[0] = __floats2bfloat162_rn(v.x, v.y);
        d[1] = __floats2bfloat162_rn(v.z, v.w);
    }

    // ---- True logits BEFORE the barrier: a-rows are L1-hot from the gather,
    //      b-rows already prefetched. 4 independent reduce chains for ILP. ----
    float tacc = 0.0f;
    #pragma unroll
    for (int i = 0; i < 4; i++) {
        int lr = ns * 32 + warp * 4 + i;
        const float* er = emb + (size_t)sRow[lr] * EMB + lane * 8;
        float4 a0 = __ldg((const float4*)er);
        float4 a1 = __ldg((const float4*)(er + 4));
        float s = a0.x * tb0[i].x;
        s = fmaf(a0.y, tb0[i].y, s); s = fmaf(a0.z, tb0[i].z, s); s = fmaf(a0.w, tb0[i].w, s);
        s = fmaf(a1.x, tb1[i].x, s); s = fmaf(a1.y, tb1[i].y, s);
        s = fmaf(a1.z, tb1[i].z, s); s = fmaf(a1.w, tb1[i].w, s);
        #pragma unroll
        for (int o = 16; o; o >>= 1) s += __shfl_xor_sync(0xFFFFFFFFu, s, o);
        if (lane == 0) {
            int lab = labv[i];
            float p = (logf((float)lab + 2.0f) - logf((float)lab + 1.0f)) * INV_LOGV;
            float t = s + nceb[lab] - logf((float)NS * p);
            tacc += softplus_fast(-t);    // sigmoid_xent(t, 1)
        }
    }
    __syncthreads();

    // ---- Sampled logits: warp (wm, wn) owns 16 rows x 64 samples ----
    const int wm = warp & 3;
    const int wn = warp >> 2;
    const int mrow  = wm * 16;
    const int nbase = wn * 64;

    float acc[8][4];
    #pragma unroll
    for (int n = 0; n < 8; n++) {
        acc[n][0] = 0.f; acc[n][1] = 0.f; acc[n][2] = 0.f; acc[n][3] = 0.f;
    }

    const int mi = lane >> 3;
    const int arow = mrow + (mi & 1) * 8 + (lane & 7);
    const int acolb = (mi >> 1) * 8;
    const int bRow = nbase + (mi >> 1) * 8 + (lane & 7);
    const int bcolb = (mi & 1) * 8;

    // Software-pipelined k-loop: fragments for step k+1 load while step k MMAs.
    uint32_t fA[2][4], fB[2][16];
    {
        ldsm_x4(fA[0][0], fA[0][1], fA[0][2], fA[0][3], smem_u32(sA + arow * KPAD + acolb));
        #pragma unroll
        for (int nn = 0; nn < 4; nn++)
            ldsm_x4(fB[0][4*nn], fB[0][4*nn+1], fB[0][4*nn+2], fB[0][4*nn+3],
                    smem_u32(sW + (bRow + nn * 16) * KPAD + bcolb));
    }
    #pragma unroll
    for (int ks = 0; ks < 16; ks++) {
        int cur = ks & 1, nxt = cur ^ 1;
        if (ks < 15) {
            int k = (ks + 1) * 16;
            ldsm_x4(fA[nxt][0], fA[nxt][1], fA[nxt][2], fA[nxt][3],
                    smem_u32(sA + arow * KPAD + k + acolb));
            #pragma unroll
            for (int nn = 0; nn < 4; nn++)
                ldsm_x4(fB[nxt][4*nn], fB[nxt][4*nn+1], fB[nxt][4*nn+2], fB[nxt][4*nn+3],
                        smem_u32(sW + (bRow + nn * 16) * KPAD + k + bcolb));
        }
        #pragma unroll
        for (int nn = 0; nn < 4; nn++) {
            mma_bf16(acc[2*nn  ][0], acc[2*nn  ][1], acc[2*nn  ][2], acc[2*nn  ][3],
                     fA[cur][0], fA[cur][1], fA[cur][2], fA[cur][3],
                     fB[cur][4*nn], fB[cur][4*nn+1]);
            mma_bf16(acc[2*nn+1][0], acc[2*nn+1][1], acc[2*nn+1][2], acc[2*nn+1][3],
                     fA[cur][0], fA[cur][1], fA[cur][2], fA[cur][3],
                     fB[cur][4*nn+2], fB[cur][4*nn+3]);
        }
    }

    // ---- Epilogue: fast softplus(logit + corr), thread-local sum ----
    const int q = lane & 3;
    float local = tacc;
    #pragma unroll
    for (int n = 0; n < 8; n++) {
        int c0 = nbase + n * 8 + q * 2;
        float k0 = sCorr[c0], k1 = sCorr[c0 + 1];
        local += softplus_fast(acc[n][0] + k0) + softplus_fast(acc[n][1] + k1)
               + softplus_fast(acc[n][2] + k0) + softplus_fast(acc[n][3] + k1);
    }

    // ---- Deterministic block reduction -> per-block partial ----
    #pragma unroll
    for (int o = 16; o; o >>= 1) local += __shfl_xor_sync(0xFFFFFFFFu, local, o);
    if (lane == 0) sRed[warp] = local;
    __syncthreads();
    __shared__ bool sLast;
    if (tid == 0) {
        float v = 0.f;
        #pragma unroll
        for (int w = 0; w < 8; w++) v += sRed[w];
        g_partials[bid] = v;
        __threadfence();
        int old = atomicAdd(&g_count, 1);
        sLast = (old == NBLK - 1);
    }
    __syncthreads();

    // ---- Last block folds all partials into the scalar (deterministic tree) ----
    if (sLast) {
        __threadfence();
        float v = g_partials[tid] + g_partials[tid + 256];
        #pragma unroll
        for (int o = 16; o; o >>= 1) v += __shfl_xor_sync(0xFFFFFFFFu, v, o);
        if (lane == 0) sRed[warp] = v;
        __syncthreads();
        if (tid == 0) {
            float t = 0.f;
            #pragma unroll
            for (int w = 0; w < 8; w++) t += sRed[w];
            out[(size_t)BATCH * EMB] = t * (1.0f / (float)BATCH);
            g_count = 0;   // reset for next graph replay
        }
    }
}

extern "C" void kernel_launch(void* const* d_in, const int* in_sizes, int n_in,
                              void* d_out, int out_size) {
    const float* emb    = (const float*)d_in[0];
    const float* ncew   = (const float*)d_in[1];
    const float* nceb   = (const float*)d_in[2];
    const int*   inputs = (const int*)d_in[3];
    const int*   labels = (const int*)d_in[4];
    const int*   sids   = (const int*)d_in[5];
    float* out = (float*)d_out;

    size_t smem = (size_t)(MBLK + NSB) * KPAD * sizeof(__nv_bfloat16)
                + (size_t)NSB * sizeof(float)
                + (size_t)MBLK * sizeof(int)
                + 8 * sizeof(float);
    cudaFuncSetAttribute(w2v_fused, cudaFuncAttributeMaxDynamicSharedMemorySize, (int)smem);
    w2v_fused<<<NBLK, 256, smem>>>(emb, ncew, nceb, inputs, labels, sids, out);
}

// round 6
// speedup vs baseline: 1.1326x; 1.0696x over previous
#include <cuda_runtime.h>
#include <cuda_bf16.h>
#include <cstdint>
#include <cstddef>

#define VOCAB   100000
#define EMB     256
#define NS      256
#define BATCH   16384
#define MBLK    64               // batch rows per block
#define NBLK    (BATCH / MBLK)   // 256 blocks, 512 threads each
#define KPAD    264              // bf16 elems per smem row (256+8 -> conflict-free ldmatrix)

__device__ float g_partials[NBLK];
__device__ int   g_count = 0;

__device__ __forceinline__ float softplus_fast(float x) {
    return fmaxf(x, 0.0f) + __logf(1.0f + __expf(-fabsf(x)));
}

__device__ __forceinline__ uint32_t smem_u32(const void* p) {
    return (uint32_t)__cvta_generic_to_shared(p);
}

__device__ __forceinline__ void ldsm_x4(uint32_t& r0, uint32_t& r1, uint32_t& r2, uint32_t& r3,
                                        uint32_t addr) {
    asm volatile("ldmatrix.sync.aligned.m8n8.x4.shared.b16 {%0,%1,%2,%3}, [%4];"
                 : "=r"(r0), "=r"(r1), "=r"(r2), "=r"(r3) : "r"(addr));
}

__device__ __forceinline__ void mma_bf16(float& c0, float& c1, float& c2, float& c3,
                                         uint32_t a0, uint32_t a1, uint32_t a2, uint32_t a3,
                                         uint32_t b0, uint32_t b1) {
    asm volatile("mma.sync.aligned.m16n8k16.row.col.f32.bf16.bf16.f32 "
                 "{%0,%1,%2,%3}, {%4,%5,%6,%7}, {%8,%9}, {%0,%1,%2,%3};"
                 : "+f"(c0), "+f"(c1), "+f"(c2), "+f"(c3)
                 : "r"(a0), "r"(a1), "r"(a2), "r"(a3), "r"(b0), "r"(b1));
}

__device__ __forceinline__ uint2 pack_bf16x4(float4 v) {
    __nv_bfloat162 p0 = __floats2bfloat162_rn(v.x, v.y);
    __nv_bfloat162 p1 = __floats2bfloat162_rn(v.z, v.w);
    uint2 u;
    u.x = *(uint32_t*)&p0;
    u.y = *(uint32_t*)&p1;
    return u;
}

__global__ void __launch_bounds__(512, 1) w2v_fused(
    const float* __restrict__ emb,
    const float* __restrict__ ncew,
    const float* __restrict__ nceb,
    const int* __restrict__ inputs,
    const int* __restrict__ labels,
    const int* __restrict__ sids,
    float* __restrict__ out)
{
    extern __shared__ unsigned char smem_raw[];
    __nv_bfloat16* sA = (__nv_bfloat16*)smem_raw;             // [MBLK][KPAD]
    __nv_bfloat16* sW = sA + MBLK * KPAD;                     // [NS][KPAD]
    float* sCorr = (float*)(sW + (size_t)NS * KPAD);          // [NS]
    int*   sRow  = (int*)(sCorr + NS);                        // [MBLK]
    float* sRed  = (float*)(sRow + MBLK);                     // [16]

    const int tid  = threadIdx.x;
    const int bid  = blockIdx.x;
    const int row0 = bid * MBLK;
    const float INV_LOGV = 1.0f / logf((float)VOCAB + 1.0f);

    if (tid < MBLK) sRow[tid] = inputs[row0 + tid];
    if (tid < NS) {
        int s = sids[tid];
        float p = (logf((float)s + 2.0f) - logf((float)s + 1.0f)) * INV_LOGV;
        sCorr[tid] = nceb[s] - logf((float)NS * p);
    }
    __syncthreads();

    const int warp = tid >> 5;   // 0..15
    const int lane = tid & 31;

    // ---- Prefetch true-logit label-weight rows (cold DRAM); latency hides
    //      under the gather burst. 4 rows per warp. ----
    int    labv[4];
    float4 tb0[4], tb1[4];
    #pragma unroll
    for (int i = 0; i < 4; i++) {
        int lr = warp * 4 + i;
        labv[i] = labels[row0 + lr];
        const float* wr = ncew + (size_t)labv[i] * EMB + lane * 8;
        tb0[i] = __ldg((const float4*)wr);
        tb1[i] = __ldg((const float4*)(wr + 4));
    }

    // ---- Gather embed rows: fp32 -> out, bf16 (STS.64) -> smem A ----
    #pragma unroll
    for (int it = 0; it < MBLK * (EMB / 4) / 512; it++) {   // 8 iters
        int i = it * 512 + tid;
        int r = i >> 6, c4 = i & 63;
        float4 v = __ldg((const float4*)(emb + (size_t)sRow[r] * EMB + c4 * 4));
        ((float4*)out)[(size_t)(row0 + r) * (EMB / 4) + c4] = v;
        *(uint2*)(sA + r * KPAD + c4 * 4) = pack_bf16x4(v);
    }
    // ---- Gather all 256 sampled weight rows -> smem W (bf16, STS.64) ----
    #pragma unroll
    for (int it = 0; it < NS * (EMB / 4) / 512; it++) {     // 32 iters
        int i = it * 512 + tid;
        int r = i >> 6, c4 = i & 63;
        int s = sids[r];
        float4 v = __ldg((const float4*)(ncew + (size_t)s * EMB + c4 * 4));
        *(uint2*)(sW + r * KPAD + c4 * 4) = pack_bf16x4(v);
    }

    // ---- True logits before the barrier (embed rows L1-hot from gather) ----
    float tacc = 0.0f;
    #pragma unroll
    for (int i = 0; i < 4; i++) {
        int lr = warp * 4 + i;
        const float* er = emb + (size_t)sRow[lr] * EMB + lane * 8;
        float4 a0 = __ldg((const float4*)er);
        float4 a1 = __ldg((const float4*)(er + 4));
        float s = a0.x * tb0[i].x;
        s = fmaf(a0.y, tb0[i].y, s); s = fmaf(a0.z, tb0[i].z, s); s = fmaf(a0.w, tb0[i].w, s);
        s = fmaf(a1.x, tb1[i].x, s); s = fmaf(a1.y, tb1[i].y, s);
        s = fmaf(a1.z, tb1[i].z, s); s = fmaf(a1.w, tb1[i].w, s);
        #pragma unroll
        for (int o = 16; o; o >>= 1) s += __shfl_xor_sync(0xFFFFFFFFu, s, o);
        if (lane == 0) {
            int lab = labv[i];
            float p = (logf((float)lab + 2.0f) - logf((float)lab + 1.0f)) * INV_LOGV;
            float t = s + nceb[lab] - logf((float)NS * p);
            tacc += softplus_fast(-t);    // sigmoid_xent(t, 1)
        }
    }
    __syncthreads();

    // ---- Sampled logits: warp (wm, wn) owns 16 rows x 64 samples ----
    const int wm = warp & 3;
    const int wn = warp >> 2;
    const int mrow  = wm * 16;
    const int nbase = wn * 64;

    float acc[8][4];
    #pragma unroll
    for (int n = 0; n < 8; n++) {
        acc[n][0] = 0.f; acc[n][1] = 0.f; acc[n][2] = 0.f; acc[n][3] = 0.f;
    }

    const int mi = lane >> 3;
    const int arow  = mrow + (mi & 1) * 8 + (lane & 7);
    const int acolb = (mi >> 1) * 8;
    const int bRow  = nbase + (mi >> 1) * 8 + (lane & 7);
    const int bcolb = (mi & 1) * 8;

    #pragma unroll
    for (int k = 0; k < EMB; k += 16) {
        uint32_t a0, a1, a2, a3;
        ldsm_x4(a0, a1, a2, a3, smem_u32(sA + arow * KPAD + k + acolb));
        #pragma unroll
        for (int nn = 0; nn < 4; nn++) {
            uint32_t b0, b1, b2, b3;
            ldsm_x4(b0, b1, b2, b3, smem_u32(sW + (bRow + nn * 16) * KPAD + k + bcolb));
            mma_bf16(acc[2*nn  ][0], acc[2*nn  ][1], acc[2*nn  ][2], acc[2*nn  ][3],
                     a0, a1, a2, a3, b0, b1);
            mma_bf16(acc[2*nn+1][0], acc[2*nn+1][1], acc[2*nn+1][2], acc[2*nn+1][3],
                     a0, a1, a2, a3, b2, b3);
        }
    }

    // ---- Epilogue: softplus via single log-of-product per thread ----
    // sum softplus(x_i) = sum max(x_i,0) + log( prod (1 + e^-|x_i|) )
    // 32 factors, each in (1,2] -> product <= 2^32, safely in fp32 range.
    const int q = lane & 3;
    float local = tacc;
    float prod = 1.0f;
    #pragma unroll
    for (int n = 0; n < 8; n++) {
        int c0 = nbase + n * 8 + q * 2;
        float k0 = sCorr[c0], k1 = sCorr[c0 + 1];
        #pragma unroll
        for (int j = 0; j < 4; j++) {
            float x = acc[n][j] + ((j & 1) ? k1 : k0);
            local += fmaxf(x, 0.0f);
            prod *= 1.0f + __expf(-fabsf(x));
        }
    }
    local += __logf(prod);

    // ---- Deterministic block reduction -> per-block partial ----
    #pragma unroll
    for (int o = 16; o; o >>= 1) local += __shfl_xor_sync(0xFFFFFFFFu, local, o);
    if (lane == 0) sRed[warp] = local;
    __syncthreads();
    __shared__ bool sLast;
    if (tid == 0) {
        float v = 0.f;
        #pragma unroll
        for (int w = 0; w < 16; w++) v += sRed[w];
        g_partials[bid] = v;
        __threadfence();
        int old = atomicAdd(&g_count, 1);
        sLast = (old == NBLK - 1);
    }
    __syncthreads();

    // ---- Last block folds all partials into the scalar (deterministic tree) ----
    if (sLast) {
        __threadfence();
        float v = (tid < NBLK) ? g_partials[tid] : 0.0f;
        #pragma unroll
        for (int o = 16; o; o >>= 1) v += __shfl_xor_sync(0xFFFFFFFFu, v, o);
        if (lane == 0) sRed[warp] = v;
        __syncthreads();
        if (tid == 0) {
            float t = 0.f;
            #pragma unroll
            for (int w = 0; w < 16; w++) t += sRed[w];
            out[(size_t)BATCH * EMB] = t * (1.0f / (float)BATCH);
            g_count = 0;   // reset for next graph replay
        }
    }
}

extern "C" void kernel_launch(void* const* d_in, const int* in_sizes, int n_in,
                              void* d_out, int out_size) {
    const float* emb    = (const float*)d_in[0];
    const float* ncew   = (const float*)d_in[1];
    const float* nceb   = (const float*)d_in[2];
    const int*   inputs = (const int*)d_in[3];
    const int*   labels = (const int*)d_in[4];
    const int*   sids   = (const int*)d_in[5];
    float* out = (float*)d_out;

    size_t smem = (size_t)(MBLK + NS) * KPAD * sizeof(__nv_bfloat16)
                + (size_t)NS * sizeof(float)
                + (size_t)MBLK * sizeof(int)
                + 16 * sizeof(float);
    cudaFuncSetAttribute(w2v_fused, cudaFuncAttributeMaxDynamicSharedMemorySize, (int)smem);
    w2v_fused<<<NBLK, 512, smem>>>(emb, ncew, nceb, inputs, labels, sids, out);
}

// round 7
// speedup vs baseline: 1.3376x; 1.1810x over previous
#include <cuda_runtime.h>
#include <cuda_bf16.h>
#include <cstdint>
#include <cstddef>

#define VOCAB   100000
#define EMB     256
#define NS      256
#define BATCH   16384
#define TBLK    128              // rows per block (2 tiles of 64)
#define MT      64               // rows per tile
#define NBLK    (BATCH / TBLK)   // 128 blocks -> single wave on 148 SMs
#define KPAD    264              // bf16 elems per smem row (256+8 -> conflict-free ldmatrix)

__device__ float g_partials[NBLK];
__device__ int   g_count = 0;

__device__ __forceinline__ float softplus_fast(float x) {
    return fmaxf(x, 0.0f) + __logf(1.0f + __expf(-fabsf(x)));
}

__device__ __forceinline__ uint32_t smem_u32(const void* p) {
    return (uint32_t)__cvta_generic_to_shared(p);
}

__device__ __forceinline__ void ldsm_x4(uint32_t& r0, uint32_t& r1, uint32_t& r2, uint32_t& r3,
                                        uint32_t addr) {
    asm volatile("ldmatrix.sync.aligned.m8n8.x4.shared.b16 {%0,%1,%2,%3}, [%4];"
                 : "=r"(r0), "=r"(r1), "=r"(r2), "=r"(r3) : "r"(addr));
}

__device__ __forceinline__ void mma_bf16(float& c0, float& c1, float& c2, float& c3,
                                         uint32_t a0, uint32_t a1, uint32_t a2, uint32_t a3,
                                         uint32_t b0, uint32_t b1) {
    asm volatile("mma.sync.aligned.m16n8k16.row.col.f32.bf16.bf16.f32 "
                 "{%0,%1,%2,%3}, {%4,%5,%6,%7}, {%8,%9}, {%0,%1,%2,%3};"
                 : "+f"(c0), "+f"(c1), "+f"(c2), "+f"(c3)
                 : "r"(a0), "r"(a1), "r"(a2), "r"(a3), "r"(b0), "r"(b1));
}

__device__ __forceinline__ uint2 pack_bf16x4(float4 v) {
    __nv_bfloat162 p0 = __floats2bfloat162_rn(v.x, v.y);
    __nv_bfloat162 p1 = __floats2bfloat162_rn(v.z, v.w);
    uint2 u;
    u.x = *(uint32_t*)&p0;
    u.y = *(uint32_t*)&p1;
    return u;
}

__global__ void __launch_bounds__(512, 1) w2v_fused(
    const float* __restrict__ emb,
    const float* __restrict__ ncew,
    const float* __restrict__ nceb,
    const int* __restrict__ inputs,
    const int* __restrict__ labels,
    const int* __restrict__ sids,
    float* __restrict__ out)
{
    extern __shared__ unsigned char smem_raw[];
    __nv_bfloat16* sA = (__nv_bfloat16*)smem_raw;             // [2][MT][KPAD]
    __nv_bfloat16* sW = sA + 2 * MT * KPAD;                   // [NS][KPAD]
    float* sCorr = (float*)(sW + (size_t)NS * KPAD);          // [NS]
    int*   sRow  = (int*)(sCorr + NS);                        // [TBLK]
    float* sRed  = (float*)(sRow + TBLK);                     // [16]

    const int tid  = threadIdx.x;
    const int bid  = blockIdx.x;
    const int R0   = bid * TBLK;
    const float INV_LOGV = 1.0f / logf((float)VOCAB + 1.0f);

    if (tid < TBLK) sRow[tid] = inputs[R0 + tid];
    if (tid < NS) {
        int s = sids[tid];
        float p = (logf((float)s + 2.0f) - logf((float)s + 1.0f)) * INV_LOGV;
        sCorr[tid] = nceb[s] - logf((float)NS * p);
    }
    __syncthreads();

    const int warp = tid >> 5;   // 0..15
    const int lane = tid & 31;

    // ================= PHASE 0: all gathers + all true logits =================
    // A tile 0: fp32 -> out, bf16 -> sA[0]
    #pragma unroll
    for (int it = 0; it < MT * (EMB / 4) / 512; it++) {     // 8 iters
        int i = it * 512 + tid;
        int r = i >> 6, c4 = i & 63;
        float4 v = __ldg((const float4*)(emb + (size_t)sRow[r] * EMB + c4 * 4));
        ((float4*)out)[(size_t)(R0 + r) * (EMB / 4) + c4] = v;
        *(uint2*)(sA + r * KPAD + c4 * 4) = pack_bf16x4(v);
    }
    // W: all 256 sampled rows, loaded ONCE for both tiles
    #pragma unroll
    for (int it = 0; it < NS * (EMB / 4) / 512; it++) {     // 32 iters
        int i = it * 512 + tid;
        int r = i >> 6, c4 = i & 63;
        int s = sids[r];
        float4 v = __ldg((const float4*)(ncew + (size_t)s * EMB + c4 * 4));
        *(uint2*)(sW + r * KPAD + c4 * 4) = pack_bf16x4(v);
    }

    // True logits for ALL 128 rows (8 per warp, two batches of 4):
    // cold label-row loads overlap the gather burst above.
    float local = 0.0f;
    #pragma unroll
    for (int b = 0; b < 2; b++) {
        int    labv[4];
        float4 tb0[4], tb1[4];
        #pragma unroll
        for (int i = 0; i < 4; i++) {
            int lr = warp * 8 + b * 4 + i;
            labv[i] = labels[R0 + lr];
            const float* wr = ncew + (size_t)labv[i] * EMB + lane * 8;
            tb0[i] = __ldg((const float4*)wr);
            tb1[i] = __ldg((const float4*)(wr + 4));
        }
        #pragma unroll
        for (int i = 0; i < 4; i++) {
            int lr = warp * 8 + b * 4 + i;
            const float* er = emb + (size_t)sRow[lr] * EMB + lane * 8;
            float4 a0 = __ldg((const float4*)er);
            float4 a1 = __ldg((const float4*)(er + 4));
            float s = a0.x * tb0[i].x;
            s = fmaf(a0.y, tb0[i].y, s); s = fmaf(a0.z, tb0[i].z, s); s = fmaf(a0.w, tb0[i].w, s);
            s = fmaf(a1.x, tb1[i].x, s); s = fmaf(a1.y, tb1[i].y, s);
            s = fmaf(a1.z, tb1[i].z, s); s = fmaf(a1.w, tb1[i].w, s);
            #pragma unroll
            for (int o = 16; o; o >>= 1) s += __shfl_xor_sync(0xFFFFFFFFu, s, o);
            if (lane == 0) {
                int lab = labv[i];
                float p = (logf((float)lab + 2.0f) - logf((float)lab + 1.0f)) * INV_LOGV;
                float t = s + nceb[lab] - logf((float)NS * p);
                local += softplus_fast(-t);    // sigmoid_xent(t, 1)
            }
        }
    }
    __syncthreads();   // sA[0] + sW ready

    // ================= TILE LOOP (pipelined) =================
    const int wm = warp & 3;
    const int wn = warp >> 2;
    const int mrow  = wm * 16;
    const int nbase = wn * 64;
    const int mi = lane >> 3;
    const int arow  = mrow + (mi & 1) * 8 + (lane & 7);
    const int acolb = (mi >> 1) * 8;
    const int bRow  = nbase + (mi >> 1) * 8 + (lane & 7);
    const int bcolb = (mi & 1) * 8;
    const int q = lane & 3;

    // Stage registers for tile-1 embed rows: LDGs issue now, consumed after
    // tile-0's MMA — latency fully hidden under compute.
    float4 st[8];
    #pragma unroll
    for (int it = 0; it < 8; it++) {
        int i = it * 512 + tid;
        int r = i >> 6, c4 = i & 63;
        st[it] = __ldg((const float4*)(emb + (size_t)sRow[MT + r] * EMB + c4 * 4));
    }

    #pragma unroll
    for (int t = 0; t < 2; t++) {
        const __nv_bfloat16* sAt = sA + t * MT * KPAD;

        float acc[8][4];
        #pragma unroll
        for (int n = 0; n < 8; n++) {
            acc[n][0] = 0.f; acc[n][1] = 0.f; acc[n][2] = 0.f; acc[n][3] = 0.f;
        }

        #pragma unroll
        for (int k = 0; k < EMB; k += 16) {
            uint32_t a0, a1, a2, a3;
            ldsm_x4(a0, a1, a2, a3, smem_u32(sAt + arow * KPAD + k + acolb));
            #pragma unroll
            for (int nn = 0; nn < 4; nn++) {
                uint32_t b0, b1, b2, b3;
                ldsm_x4(b0, b1, b2, b3, smem_u32(sW + (bRow + nn * 16) * KPAD + k + bcolb));
                mma_bf16(acc[2*nn  ][0], acc[2*nn  ][1], acc[2*nn  ][2], acc[2*nn  ][3],
                         a0, a1, a2, a3, b0, b1);
                mma_bf16(acc[2*nn+1][0], acc[2*nn+1][1], acc[2*nn+1][2], acc[2*nn+1][3],
                         a0, a1, a2, a3, b2, b3);
            }
        }

        // Epilogue: sum max(x,0) + log(prod(1+e^-|x|)) — one __logf per tile
        float prod = 1.0f;
        #pragma unroll
        for (int n = 0; n < 8; n++) {
            int c0 = nbase + n * 8 + q * 2;
            float k0 = sCorr[c0], k1 = sCorr[c0 + 1];
            #pragma unroll
            for (int j = 0; j < 4; j++) {
                float x = acc[n][j] + ((j & 1) ? k1 : k0);
                local += fmaxf(x, 0.0f);
                prod *= 1.0f + __expf(-fabsf(x));
            }
        }
        local += __logf(prod);

        if (t == 0) {
            // Drain stage: fp32 -> out, bf16 -> sA[1]
            #pragma unroll
            for (int it = 0; it < 8; it++) {
                int i = it * 512 + tid;
                int r = i >> 6, c4 = i & 63;
                ((float4*)out)[(size_t)(R0 + MT + r) * (EMB / 4) + c4] = st[it];
                *(uint2*)(sA + MT * KPAD + r * KPAD + c4 * 4) = pack_bf16x4(st[it]);
            }
            __syncthreads();
        }
    }

    // ---- Deterministic block reduction -> per-block partial ----
    #pragma unroll
    for (int o = 16; o; o >>= 1) local += __shfl_xor_sync(0xFFFFFFFFu, local, o);
    if (lane == 0) sRed[warp] = local;
    __syncthreads();
    __shared__ bool sLast;
    if (tid == 0) {
        float v = 0.f;
        #pragma unroll
        for (int w = 0; w < 16; w++) v += sRed[w];
        g_partials[bid] = v;
        __threadfence();
        int old = atomicAdd(&g_count, 1);
        sLast = (old == NBLK - 1);
    }
    __syncthreads();

    // ---- Last block folds all partials into the scalar ----
    if (sLast) {
        __threadfence();
        float v = (tid < NBLK) ? g_partials[tid] : 0.0f;
        #pragma unroll
        for (int o = 16; o; o >>= 1) v += __shfl_xor_sync(0xFFFFFFFFu, v, o);
        if (lane == 0) sRed[warp] = v;
        __syncthreads();
        if (tid == 0) {
            float t = 0.f;
            #pragma unroll
            for (int w = 0; w < 16; w++) t += sRed[w];
            out[(size_t)BATCH * EMB] = t * (1.0f / (float)BATCH);
            g_count = 0;   // reset for next graph replay
        }
    }
}

extern "C" void kernel_launch(void* const* d_in, const int* in_sizes, int n_in,
                              void* d_out, int out_size) {
    const float* emb    = (const float*)d_in[0];
    const float* ncew   = (const float*)d_in[1];
    const float* nceb   = (const float*)d_in[2];
    const int*   inputs = (const int*)d_in[3];
    const int*   labels = (const int*)d_in[4];
    const int*   sids   = (const int*)d_in[5];
    float* out = (float*)d_out;

    size_t smem = (size_t)(2 * MT + NS) * KPAD * sizeof(__nv_bfloat16)
                + (size_t)NS * sizeof(float)
                + (size_t)TBLK * sizeof(int)
                + 16 * sizeof(float);
    cudaFuncSetAttribute(w2v_fused, cudaFuncAttributeMaxDynamicSharedMemorySize, (int)smem);
    w2v_fused<<<NBLK, 512, smem>>>(emb, ncew, nceb, inputs, labels, sids, out);
}